// round 4
// baseline (speedup 1.0000x reference)
#include <cuda_runtime.h>
#include <cstdint>

#define FULL 0xffffffffu

constexpr int N = 65536;
constexpr int D = 512;

constexpr int TPB   = 256;                         // 8 warps
constexpr int GRID  = 592;                         // 4 CTAs/SM * 148 SMs
constexpr int TILE_ROWS  = 8;                      // one row per warp per tile
constexpr int TILE_BYTES = TILE_ROWS * D * 4;      // 16384
constexpr int NTILES     = N / TILE_ROWS;          // 8192
constexpr int K45_BLOCKS = 64;                     // all resident (<148)

// Scratch (allocation-free: __device__ globals)
__device__ __align__(16) float g_s[D];
__device__ __align__(16) float g_t[D];
__device__ float    g_c;
__device__ unsigned g_maxkey;
__device__ float    g_sumexp;
__device__ unsigned g_done;
__device__ __align__(16) float g_x[N];

// ---------------------------------------------------------------------------
// PTX helpers: mbarrier + cp.async.bulk (global -> shared)
// ---------------------------------------------------------------------------
__device__ __forceinline__ uint32_t smem_u32(const void* p) {
    return (uint32_t)__cvta_generic_to_shared(p);
}
__device__ __forceinline__ void mbar_init(uint32_t mbar, uint32_t cnt) {
    asm volatile("mbarrier.init.shared.b64 [%0], %1;" :: "r"(mbar), "r"(cnt) : "memory");
}
__device__ __forceinline__ void mbar_expect_tx(uint32_t mbar, uint32_t bytes) {
    asm volatile("mbarrier.arrive.expect_tx.shared.b64 _, [%0], %1;"
                 :: "r"(mbar), "r"(bytes) : "memory");
}
__device__ __forceinline__ void bulk_g2s(uint32_t dst, const void* src,
                                         uint32_t bytes, uint32_t mbar) {
    asm volatile(
        "cp.async.bulk.shared::cluster.global.mbarrier::complete_tx::bytes "
        "[%0], [%1], %2, [%3];"
        :: "r"(dst), "l"(src), "r"(bytes), "r"(mbar) : "memory");
}
__device__ __forceinline__ void mbar_wait(uint32_t mbar, uint32_t phase) {
    uint32_t done;
    do {
        asm volatile(
            "{\n\t.reg .pred p;\n\t"
            "mbarrier.try_wait.parity.shared.b64 p, [%1], %2;\n\t"
            "selp.b32 %0, 1, 0, p;\n\t}"
            : "=r"(done) : "r"(mbar), "r"(phase) : "memory");
    } while (!done);
}

__device__ __forceinline__ float warp_sum(float v) {
#pragma unroll
    for (int o = 16; o; o >>= 1) v += __shfl_xor_sync(FULL, v, o);
    return v;
}
__device__ __forceinline__ float dot4(float4 a, float4 w) {
    return fmaf(a.w, w.w, fmaf(a.z, w.z, fmaf(a.y, w.y, a.x * w.x)));
}

// ---------------------------------------------------------------------------
// K0: zero accumulators (graph is replayed; reset every call)
// ---------------------------------------------------------------------------
__global__ void k_init() {
    int t = threadIdx.x;
    g_s[t] = 0.0f;
    g_t[t] = 0.0f;
    if (t == 0) { g_c = 0.0f; g_maxkey = 0u; g_sumexp = 0.0f; g_done = 0u; }
}

// ---------------------------------------------------------------------------
// K1: pass 1 with bulk-copy double-buffered smem pipeline.
// Per row n: k = inputs[n]·key_w + key_b; s += inputs[n]*k.
// Tile = 8 rows (16KB); warp w computes row w of the tile.
// ---------------------------------------------------------------------------
__global__ void __launch_bounds__(TPB, 4)
k1(const float* __restrict__ inp, const float* __restrict__ kw,
   const float* __restrict__ kb) {
    __shared__ __align__(128) char buf[2 * TILE_BYTES];
    __shared__ __align__(8) unsigned long long mbar_s[2];
    __shared__ float sred[D];

    const int tid  = threadIdx.x;
    const int lane = tid & 31;
    const int warp = tid >> 5;
    const int bid  = blockIdx.x;

    const uint32_t mb0 = smem_u32(&mbar_s[0]);
    const uint32_t mb1 = smem_u32(&mbar_s[1]);
    const uint32_t sb  = smem_u32(buf);

    if (tid == 0) {
        mbar_init(mb0, 1);
        mbar_init(mb1, 1);
        asm volatile("fence.proxy.async.shared::cta;" ::: "memory");
    }
    sred[tid] = 0.0f; sred[tid + 256] = 0.0f;
    __syncthreads();

    const float4* __restrict__ kw4 = (const float4*)kw;
    const float4 w0 = kw4[lane],      w1 = kw4[lane + 32],
                 w2 = kw4[lane + 64], w3 = kw4[lane + 96];
    const float kb0 = kb[0];

    // prologue: issue first tile into slot 0
    if (tid == 0 && bid < NTILES) {
        mbar_expect_tx(mb0, TILE_BYTES);
        bulk_g2s(sb, inp + (size_t)bid * TILE_ROWS * D, TILE_BYTES, mb0);
    }

    float4 s0 = {0,0,0,0}, s1 = {0,0,0,0}, s2 = {0,0,0,0}, s3 = {0,0,0,0};

    int i = 0;
    for (int t = bid; t < NTILES; t += GRID, i++) {
        // issue next tile into the other slot (freed by previous iteration's sync)
        const int nt = t + GRID;
        if (tid == 0 && nt < NTILES) {
            const int so = (i + 1) & 1;
            const uint32_t mb = so ? mb1 : mb0;
            mbar_expect_tx(mb, TILE_BYTES);
            bulk_g2s(sb + so * TILE_BYTES, inp + (size_t)nt * TILE_ROWS * D,
                     TILE_BYTES, mb);
        }
        const int s = i & 1;
        mbar_wait(s ? mb1 : mb0, (i >> 1) & 1);

        const float4* __restrict__ row =
            (const float4*)(buf + s * TILE_BYTES + warp * (D * 4));
        const float4 a0 = row[lane],      a1 = row[lane + 32],
                     a2 = row[lane + 64], a3 = row[lane + 96];

        float d = (dot4(a0, w0) + dot4(a1, w1)) + (dot4(a2, w2) + dot4(a3, w3));
        d = warp_sum(d);
        const float kv = d + kb0;

        s0.x = fmaf(a0.x, kv, s0.x); s0.y = fmaf(a0.y, kv, s0.y);
        s0.z = fmaf(a0.z, kv, s0.z); s0.w = fmaf(a0.w, kv, s0.w);
        s1.x = fmaf(a1.x, kv, s1.x); s1.y = fmaf(a1.y, kv, s1.y);
        s1.z = fmaf(a1.z, kv, s1.z); s1.w = fmaf(a1.w, kv, s1.w);
        s2.x = fmaf(a2.x, kv, s2.x); s2.y = fmaf(a2.y, kv, s2.y);
        s2.z = fmaf(a2.z, kv, s2.z); s2.w = fmaf(a2.w, kv, s2.w);
        s3.x = fmaf(a3.x, kv, s3.x); s3.y = fmaf(a3.y, kv, s3.y);
        s3.z = fmaf(a3.z, kv, s3.z); s3.w = fmaf(a3.w, kv, s3.w);

        __syncthreads();   // slot s fully consumed -> reusable next iteration
    }

    // block pre-reduction in shared, then 512 global atomics per block
    const int b0i = 4 * lane;
    atomicAdd(&sred[b0i + 0],       s0.x); atomicAdd(&sred[b0i + 1],       s0.y);
    atomicAdd(&sred[b0i + 2],       s0.z); atomicAdd(&sred[b0i + 3],       s0.w);
    atomicAdd(&sred[128 + b0i + 0], s1.x); atomicAdd(&sred[128 + b0i + 1], s1.y);
    atomicAdd(&sred[128 + b0i + 2], s1.z); atomicAdd(&sred[128 + b0i + 3], s1.w);
    atomicAdd(&sred[256 + b0i + 0], s2.x); atomicAdd(&sred[256 + b0i + 1], s2.y);
    atomicAdd(&sred[256 + b0i + 2], s2.z); atomicAdd(&sred[256 + b0i + 3], s2.w);
    atomicAdd(&sred[384 + b0i + 0], s3.x); atomicAdd(&sred[384 + b0i + 1], s3.y);
    atomicAdd(&sred[384 + b0i + 2], s3.z); atomicAdd(&sred[384 + b0i + 3], s3.w);
    __syncthreads();
    atomicAdd(&g_s[tid], sred[tid]);
    atomicAdd(&g_s[tid + 256], sred[tid + 256]);
}

// ---------------------------------------------------------------------------
// K2: t[d] = sum_j value_w[j][d] * s[j]  (32 blocks, 16 j's each, atomic merge)
//     c    = value_b · s                 (block 0)
// ---------------------------------------------------------------------------
__global__ void k2(const float* __restrict__ vw, const float* __restrict__ vb) {
    const int tid = threadIdx.x;            // 512 threads
    const int j0 = blockIdx.x * 16;
    float acc = 0.0f;
#pragma unroll
    for (int j = 0; j < 16; j++)
        acc = fmaf(vw[(size_t)(j0 + j) * D + tid], g_s[j0 + j], acc);
    atomicAdd(&g_t[tid], acc);

    if (blockIdx.x == 0) {
        __shared__ float red[D];
        red[tid] = vb[tid] * g_s[tid];
        __syncthreads();
        for (int sft = 256; sft > 0; sft >>= 1) {
            if (tid < sft) red[tid] += red[tid + sft];
            __syncthreads();
        }
        if (tid == 0) g_c = red[0];
    }
}

// ---------------------------------------------------------------------------
// K3: pass 2 with the same bulk-copy pipeline: x[n] = inputs[n]·t + c, max.
// ---------------------------------------------------------------------------
__global__ void __launch_bounds__(TPB, 4)
k3(const float* __restrict__ inp) {
    __shared__ __align__(128) char buf[2 * TILE_BYTES];
    __shared__ __align__(8) unsigned long long mbar_s[2];

    const int tid  = threadIdx.x;
    const int lane = tid & 31;
    const int warp = tid >> 5;
    const int bid  = blockIdx.x;

    const uint32_t mb0 = smem_u32(&mbar_s[0]);
    const uint32_t mb1 = smem_u32(&mbar_s[1]);
    const uint32_t sb  = smem_u32(buf);

    if (tid == 0) {
        mbar_init(mb0, 1);
        mbar_init(mb1, 1);
        asm volatile("fence.proxy.async.shared::cta;" ::: "memory");
    }
    __syncthreads();

    const float4* __restrict__ tp = (const float4*)g_t;
    const float4 w0 = tp[lane],      w1 = tp[lane + 32],
                 w2 = tp[lane + 64], w3 = tp[lane + 96];
    const float c = g_c;
    float maxv = -3.4e38f;

    if (tid == 0 && bid < NTILES) {
        mbar_expect_tx(mb0, TILE_BYTES);
        bulk_g2s(sb, inp + (size_t)bid * TILE_ROWS * D, TILE_BYTES, mb0);
    }

    int i = 0;
    for (int t = bid; t < NTILES; t += GRID, i++) {
        const int nt = t + GRID;
        if (tid == 0 && nt < NTILES) {
            const int so = (i + 1) & 1;
            const uint32_t mb = so ? mb1 : mb0;
            mbar_expect_tx(mb, TILE_BYTES);
            bulk_g2s(sb + so * TILE_BYTES, inp + (size_t)nt * TILE_ROWS * D,
                     TILE_BYTES, mb);
        }
        const int s = i & 1;
        mbar_wait(s ? mb1 : mb0, (i >> 1) & 1);

        const float4* __restrict__ row =
            (const float4*)(buf + s * TILE_BYTES + warp * (D * 4));
        const float4 a0 = row[lane],      a1 = row[lane + 32],
                     a2 = row[lane + 64], a3 = row[lane + 96];

        float d = (dot4(a0, w0) + dot4(a1, w1)) + (dot4(a2, w2) + dot4(a3, w3));
        d = warp_sum(d);
        const float x = d + c;
        if (lane == 0) g_x[t * TILE_ROWS + warp] = x;
        maxv = fmaxf(maxv, x);

        __syncthreads();
    }

    if (lane == 0) {
        unsigned u = __float_as_uint(maxv);
        unsigned key = (u & 0x80000000u) ? ~u : (u | 0x80000000u);
        atomicMax(&g_maxkey, key);
    }
}

// ---------------------------------------------------------------------------
// K45: fused exp/sum/divide. 64 fully-resident blocks; internal spin barrier.
// ---------------------------------------------------------------------------
__global__ void k45(float* __restrict__ out) {
    const unsigned key = g_maxkey;
    const unsigned ub = (key & 0x80000000u) ? (key & 0x7fffffffu) : ~key;
    const float gmax = __uint_as_float(ub);

    const int i = blockIdx.x * blockDim.x + threadIdx.x;   // 16384 threads
    const float4 v = ((const float4*)g_x)[i];
    float4 e;
    e.x = expf(v.x - gmax); e.y = expf(v.y - gmax);
    e.z = expf(v.z - gmax); e.w = expf(v.w - gmax);

    float ws = warp_sum((e.x + e.y) + (e.z + e.w));
    __shared__ float sh[8];
    const int lane = threadIdx.x & 31, w = threadIdx.x >> 5;
    if (lane == 0) sh[w] = ws;
    __syncthreads();
    if (w == 0) {
        float s = (lane < 8) ? sh[lane] : 0.0f;
        s = warp_sum(s);
        if (lane == 0) {
            atomicAdd(&g_sumexp, s);
            __threadfence();
            atomicAdd(&g_done, 1u);
        }
    }

    // grid-wide spin: all 64 CTAs resident, so this cannot deadlock
    if (threadIdx.x == 0) {
        while (*((volatile unsigned*)&g_done) < (unsigned)gridDim.x) { }
    }
    __syncthreads();
    __threadfence();

    const float inv = 1.0f / (*((volatile float*)&g_sumexp));
    float4 r;
    r.x = e.x * inv; r.y = e.y * inv; r.z = e.z * inv; r.w = e.w * inv;
    ((float4*)out)[i] = r;
}

// ---------------------------------------------------------------------------
extern "C" void kernel_launch(void* const* d_in, const int* in_sizes, int n_in,
                              void* d_out, int out_size) {
    (void)in_sizes; (void)n_in; (void)out_size;
    const float* inp = (const float*)d_in[0];   // [N, D]
    const float* kw  = (const float*)d_in[1];   // [1, D]
    const float* kb  = (const float*)d_in[2];   // [1]
    const float* vw  = (const float*)d_in[3];   // [D, D]
    const float* vb  = (const float*)d_in[4];   // [D]
    float* out = (float*)d_out;                 // [N, 1]

    k_init<<<1, D>>>();
    k1<<<GRID, TPB>>>(inp, kw, kb);
    k2<<<32, D>>>(vw, vb);
    k3<<<GRID, TPB>>>(inp);
    k45<<<K45_BLOCKS, TPB>>>(out);
}

// round 5
// speedup vs baseline: 1.0213x; 1.0213x over previous
#include <cuda_runtime.h>
#include <cstdint>

#define FULL 0xffffffffu

constexpr int N = 65536;
constexpr int D = 512;

constexpr int TPB = 256;                    // 8 warps/block
constexpr int CHUNK_ROWS = 16;              // 8 warps x 2 rows (one pair/warp)
constexpr int NCHUNKS = N / CHUNK_ROWS;     // 4096
constexpr int K1_BLOCKS = 444;              // 3 CTAs/SM * 148
constexpr int K3_BLOCKS = 592;              // 4 CTAs/SM * 148
constexpr int K45_BLOCKS = 64;              // all resident (<148)

// Scratch (allocation-free: __device__ globals)
__device__ __align__(16) float g_s[D];
__device__ __align__(16) float g_t[D];
__device__ float    g_c;
__device__ unsigned g_maxkey;
__device__ float    g_sumexp;
__device__ unsigned g_done;
__device__ unsigned g_tk1;
__device__ unsigned g_tk3;
__device__ __align__(16) float g_x[N];

__device__ __forceinline__ float warp_sum(float v) {
#pragma unroll
    for (int o = 16; o; o >>= 1) v += __shfl_xor_sync(FULL, v, o);
    return v;
}
__device__ __forceinline__ float dot4(float4 a, float4 w) {
    return fmaf(a.w, w.w, fmaf(a.z, w.z, fmaf(a.y, w.y, a.x * w.x)));
}

// ---------------------------------------------------------------------------
// K0: zero accumulators + ticket counters (graph is replayed; reset each call)
// ---------------------------------------------------------------------------
__global__ void k_init() {
    int t = threadIdx.x;
    g_s[t] = 0.0f;
    g_t[t] = 0.0f;
    if (t == 0) {
        g_c = 0.0f; g_maxkey = 0u; g_sumexp = 0.0f; g_done = 0u;
        g_tk1 = 0u; g_tk3 = 0u;
    }
}

// ---------------------------------------------------------------------------
// K1: pass 1. Per row n: k = inputs[n]·key_w + key_b; s += inputs[n]*k.
// Dynamic ticket per 16-row chunk; warp w does rows {2w, 2w+1} of the chunk.
// 8 front-batched LDG.128 per warp-iteration.
// ---------------------------------------------------------------------------
__global__ void __launch_bounds__(TPB, 3)
k1(const float* __restrict__ inp, const float* __restrict__ kw,
   const float* __restrict__ kb) {
    __shared__ float sred[D];
    __shared__ unsigned s_chunk;

    const int tid  = threadIdx.x;
    const int lane = tid & 31;
    const int warp = tid >> 5;

    for (int i = tid; i < D; i += TPB) sred[i] = 0.0f;
    if (tid == 0) s_chunk = atomicAdd(&g_tk1, 1u);
    __syncthreads();

    const float4* __restrict__ kw4 = (const float4*)kw;
    const float4 w0 = kw4[lane],      w1 = kw4[lane + 32],
                 w2 = kw4[lane + 64], w3 = kw4[lane + 96];
    const float kb0 = kb[0];

    float4 s0 = {0,0,0,0}, s1 = {0,0,0,0}, s2 = {0,0,0,0}, s3 = {0,0,0,0};

    unsigned chunk = s_chunk;
    while (chunk < (unsigned)NCHUNKS) {
        const size_t row0 = (size_t)chunk * CHUNK_ROWS + 2 * warp;
        const float4* __restrict__ rA = (const float4*)inp + row0 * (D / 4);
        const float4* __restrict__ rB = rA + (D / 4);
        const float4 a0 = rA[lane],      a1 = rA[lane + 32],
                     a2 = rA[lane + 64], a3 = rA[lane + 96];
        const float4 b0 = rB[lane],      b1 = rB[lane + 32],
                     b2 = rB[lane + 64], b3 = rB[lane + 96];

        float dA = (dot4(a0, w0) + dot4(a1, w1)) + (dot4(a2, w2) + dot4(a3, w3));
        float dB = (dot4(b0, w0) + dot4(b1, w1)) + (dot4(b2, w2) + dot4(b3, w3));
#pragma unroll
        for (int o = 16; o; o >>= 1) {
            dA += __shfl_xor_sync(FULL, dA, o);
            dB += __shfl_xor_sync(FULL, dB, o);
        }
        const float kvA = dA + kb0;
        const float kvB = dB + kb0;

        s0.x = fmaf(a0.x, kvA, fmaf(b0.x, kvB, s0.x));
        s0.y = fmaf(a0.y, kvA, fmaf(b0.y, kvB, s0.y));
        s0.z = fmaf(a0.z, kvA, fmaf(b0.z, kvB, s0.z));
        s0.w = fmaf(a0.w, kvA, fmaf(b0.w, kvB, s0.w));
        s1.x = fmaf(a1.x, kvA, fmaf(b1.x, kvB, s1.x));
        s1.y = fmaf(a1.y, kvA, fmaf(b1.y, kvB, s1.y));
        s1.z = fmaf(a1.z, kvA, fmaf(b1.z, kvB, s1.z));
        s1.w = fmaf(a1.w, kvA, fmaf(b1.w, kvB, s1.w));
        s2.x = fmaf(a2.x, kvA, fmaf(b2.x, kvB, s2.x));
        s2.y = fmaf(a2.y, kvA, fmaf(b2.y, kvB, s2.y));
        s2.z = fmaf(a2.z, kvA, fmaf(b2.z, kvB, s2.z));
        s2.w = fmaf(a2.w, kvA, fmaf(b2.w, kvB, s2.w));
        s3.x = fmaf(a3.x, kvA, fmaf(b3.x, kvB, s3.x));
        s3.y = fmaf(a3.y, kvA, fmaf(b3.y, kvB, s3.y));
        s3.z = fmaf(a3.z, kvA, fmaf(b3.z, kvB, s3.z));
        s3.w = fmaf(a3.w, kvA, fmaf(b3.w, kvB, s3.w));

        __syncthreads();                       // everyone done with s_chunk
        if (tid == 0) s_chunk = atomicAdd(&g_tk1, 1u);
        __syncthreads();
        chunk = s_chunk;
    }

    // block pre-reduction in shared, then 512 global atomics per block
    const int b0i = 4 * lane;
    atomicAdd(&sred[b0i + 0],       s0.x); atomicAdd(&sred[b0i + 1],       s0.y);
    atomicAdd(&sred[b0i + 2],       s0.z); atomicAdd(&sred[b0i + 3],       s0.w);
    atomicAdd(&sred[128 + b0i + 0], s1.x); atomicAdd(&sred[128 + b0i + 1], s1.y);
    atomicAdd(&sred[128 + b0i + 2], s1.z); atomicAdd(&sred[128 + b0i + 3], s1.w);
    atomicAdd(&sred[256 + b0i + 0], s2.x); atomicAdd(&sred[256 + b0i + 1], s2.y);
    atomicAdd(&sred[256 + b0i + 2], s2.z); atomicAdd(&sred[256 + b0i + 3], s2.w);
    atomicAdd(&sred[384 + b0i + 0], s3.x); atomicAdd(&sred[384 + b0i + 1], s3.y);
    atomicAdd(&sred[384 + b0i + 2], s3.z); atomicAdd(&sred[384 + b0i + 3], s3.w);
    __syncthreads();
    for (int i = tid; i < D; i += TPB) atomicAdd(&g_s[i], sred[i]);
}

// ---------------------------------------------------------------------------
// K2: t[d] = sum_j value_w[j][d] * s[j]  (32 blocks, 16 j's each, atomic merge)
//     c    = value_b · s                 (block 0)
// ---------------------------------------------------------------------------
__global__ void k2(const float* __restrict__ vw, const float* __restrict__ vb) {
    const int tid = threadIdx.x;            // 512 threads
    const int j0 = blockIdx.x * 16;
    float acc = 0.0f;
#pragma unroll
    for (int j = 0; j < 16; j++)
        acc = fmaf(vw[(size_t)(j0 + j) * D + tid], g_s[j0 + j], acc);
    atomicAdd(&g_t[tid], acc);

    if (blockIdx.x == 0) {
        __shared__ float red[D];
        red[tid] = vb[tid] * g_s[tid];
        __syncthreads();
        for (int sft = 256; sft > 0; sft >>= 1) {
            if (tid < sft) red[tid] += red[tid + sft];
            __syncthreads();
        }
        if (tid == 0) g_c = red[0];
    }
}

// ---------------------------------------------------------------------------
// K3: pass 2: x[n] = inputs[n]·t + c, global max. Same ticketed chunking.
// ---------------------------------------------------------------------------
__global__ void __launch_bounds__(TPB, 4)
k3(const float* __restrict__ inp) {
    __shared__ unsigned s_chunk;

    const int tid  = threadIdx.x;
    const int lane = tid & 31;
    const int warp = tid >> 5;

    if (tid == 0) s_chunk = atomicAdd(&g_tk3, 1u);
    __syncthreads();

    const float4* __restrict__ tp = (const float4*)g_t;
    const float4 w0 = tp[lane],      w1 = tp[lane + 32],
                 w2 = tp[lane + 64], w3 = tp[lane + 96];
    const float c = g_c;
    float maxv = -3.4e38f;

    unsigned chunk = s_chunk;
    while (chunk < (unsigned)NCHUNKS) {
        const size_t row0 = (size_t)chunk * CHUNK_ROWS + 2 * warp;
        const float4* __restrict__ rA = (const float4*)inp + row0 * (D / 4);
        const float4* __restrict__ rB = rA + (D / 4);
        const float4 a0 = rA[lane],      a1 = rA[lane + 32],
                     a2 = rA[lane + 64], a3 = rA[lane + 96];
        const float4 b0 = rB[lane],      b1 = rB[lane + 32],
                     b2 = rB[lane + 64], b3 = rB[lane + 96];

        float dA = (dot4(a0, w0) + dot4(a1, w1)) + (dot4(a2, w2) + dot4(a3, w3));
        float dB = (dot4(b0, w0) + dot4(b1, w1)) + (dot4(b2, w2) + dot4(b3, w3));
#pragma unroll
        for (int o = 16; o; o >>= 1) {
            dA += __shfl_xor_sync(FULL, dA, o);
            dB += __shfl_xor_sync(FULL, dB, o);
        }
        const float xA = dA + c;
        const float xB = dB + c;
        if (lane == 0) {
            g_x[row0]     = xA;
            g_x[row0 + 1] = xB;
        }
        maxv = fmaxf(maxv, fmaxf(xA, xB));

        __syncthreads();
        if (tid == 0) s_chunk = atomicAdd(&g_tk3, 1u);
        __syncthreads();
        chunk = s_chunk;
    }

    if (lane == 0) {
        unsigned u = __float_as_uint(maxv);
        unsigned key = (u & 0x80000000u) ? ~u : (u | 0x80000000u);
        atomicMax(&g_maxkey, key);
    }
}

// ---------------------------------------------------------------------------
// K45: fused exp/sum/divide. 64 fully-resident blocks; internal spin barrier.
// ---------------------------------------------------------------------------
__global__ void k45(float* __restrict__ out) {
    const unsigned key = g_maxkey;
    const unsigned ub = (key & 0x80000000u) ? (key & 0x7fffffffu) : ~key;
    const float gmax = __uint_as_float(ub);

    const int i = blockIdx.x * blockDim.x + threadIdx.x;   // 16384 threads
    const float4 v = ((const float4*)g_x)[i];
    float4 e;
    e.x = expf(v.x - gmax); e.y = expf(v.y - gmax);
    e.z = expf(v.z - gmax); e.w = expf(v.w - gmax);

    float ws = warp_sum((e.x + e.y) + (e.z + e.w));
    __shared__ float sh[8];
    const int lane = threadIdx.x & 31, w = threadIdx.x >> 5;
    if (lane == 0) sh[w] = ws;
    __syncthreads();
    if (w == 0) {
        float s = (lane < 8) ? sh[lane] : 0.0f;
        s = warp_sum(s);
        if (lane == 0) {
            atomicAdd(&g_sumexp, s);
            __threadfence();
            atomicAdd(&g_done, 1u);
        }
    }

    // grid-wide spin: all 64 CTAs resident, cannot deadlock
    if (threadIdx.x == 0) {
        while (*((volatile unsigned*)&g_done) < (unsigned)gridDim.x) { }
    }
    __syncthreads();
    __threadfence();

    const float inv = 1.0f / (*((volatile float*)&g_sumexp));
    float4 r;
    r.x = e.x * inv; r.y = e.y * inv; r.z = e.z * inv; r.w = e.w * inv;
    ((float4*)out)[i] = r;
}

// ---------------------------------------------------------------------------
extern "C" void kernel_launch(void* const* d_in, const int* in_sizes, int n_in,
                              void* d_out, int out_size) {
    (void)in_sizes; (void)n_in; (void)out_size;
    const float* inp = (const float*)d_in[0];   // [N, D]
    const float* kw  = (const float*)d_in[1];   // [1, D]
    const float* kb  = (const float*)d_in[2];   // [1]
    const float* vw  = (const float*)d_in[3];   // [D, D]
    const float* vb  = (const float*)d_in[4];   // [D]
    float* out = (float*)d_out;                 // [N, 1]

    k_init<<<1, D>>>();
    k1<<<K1_BLOCKS, TPB>>>(inp, kw, kb);
    k2<<<32, D>>>(vw, vb);
    k3<<<K3_BLOCKS, TPB>>>(inp);
    k45<<<K45_BLOCKS, TPB>>>(out);
}

// round 6
// speedup vs baseline: 1.4038x; 1.3745x over previous
#include <cuda_runtime.h>
#include <cstdint>

#define FULL 0xffffffffu

constexpr int N = 65536;
constexpr int D = 512;
constexpr int NPAIRS = N / 2;              // 32768 row pairs

constexpr int TPB = 256;                   // 8 warps/block
constexpr int K1_BLOCKS = 444;             // 3 CTAs/SM * 148 SMs (fully resident)
constexpr int K1_WARPS  = K1_BLOCKS * (TPB / 32);   // 3552
constexpr int K3_BLOCKS = 592;             // 4 CTAs/SM * 148 SMs
constexpr int K3_WARPS  = K3_BLOCKS * (TPB / 32);   // 4736
constexpr int K45_BLOCKS = 64;             // all resident (<148)

// Scratch (allocation-free: __device__ globals)
__device__ __align__(16) float g_s[D];
__device__ __align__(16) float g_t[D];
__device__ float    g_c;
__device__ unsigned g_maxkey;
__device__ float    g_sumexp;
__device__ unsigned g_done;
__device__ __align__(16) float g_x[N];

__device__ __forceinline__ float warp_sum(float v) {
#pragma unroll
    for (int o = 16; o; o >>= 1) v += __shfl_xor_sync(FULL, v, o);
    return v;
}
__device__ __forceinline__ float dot4(float4 a, float4 w) {
    return fmaf(a.w, w.w, fmaf(a.z, w.z, fmaf(a.y, w.y, a.x * w.x)));
}

// ---------------------------------------------------------------------------
// K0: zero accumulators (graph is replayed; reset every call)
// ---------------------------------------------------------------------------
__global__ void k_init() {
    int t = threadIdx.x;
    g_s[t] = 0.0f;
    g_t[t] = 0.0f;
    if (t == 0) { g_c = 0.0f; g_maxkey = 0u; g_sumexp = 0.0f; g_done = 0u; }
}

// ---------------------------------------------------------------------------
// K1: pass 1, ASCENDING row order.
// Per row n: k = inputs[n]·key_w + key_b; s += inputs[n]*k.
// Persistent grid-stride over row PAIRS; 8 front-batched LDG.128 per iter.
// ---------------------------------------------------------------------------
__global__ void __launch_bounds__(TPB, 3)
k1(const float* __restrict__ inp, const float* __restrict__ kw,
   const float* __restrict__ kb) {
    __shared__ float sblk[D];
    const int tid = threadIdx.x;
    for (int i = tid; i < D; i += TPB) sblk[i] = 0.0f;
    __syncthreads();

    const int lane = tid & 31;
    const int gw = (blockIdx.x * TPB + tid) >> 5;

    const float4* __restrict__ kw4 = (const float4*)kw;
    const float4 w0 = kw4[lane],      w1 = kw4[lane + 32],
                 w2 = kw4[lane + 64], w3 = kw4[lane + 96];
    const float kb0 = kb[0];

    float4 s0 = {0,0,0,0}, s1 = {0,0,0,0}, s2 = {0,0,0,0}, s3 = {0,0,0,0};

    for (int p = gw; p < NPAIRS; p += K1_WARPS) {
        const float4* __restrict__ rA = (const float4*)inp + (size_t)(2 * p) * (D / 4);
        const float4* __restrict__ rB = rA + (D / 4);
        const float4 a0 = rA[lane],      a1 = rA[lane + 32],
                     a2 = rA[lane + 64], a3 = rA[lane + 96];
        const float4 b0 = rB[lane],      b1 = rB[lane + 32],
                     b2 = rB[lane + 64], b3 = rB[lane + 96];

        float dA = (dot4(a0, w0) + dot4(a1, w1)) + (dot4(a2, w2) + dot4(a3, w3));
        float dB = (dot4(b0, w0) + dot4(b1, w1)) + (dot4(b2, w2) + dot4(b3, w3));
#pragma unroll
        for (int o = 16; o; o >>= 1) {
            dA += __shfl_xor_sync(FULL, dA, o);
            dB += __shfl_xor_sync(FULL, dB, o);
        }
        const float kvA = dA + kb0;
        const float kvB = dB + kb0;

        s0.x = fmaf(a0.x, kvA, fmaf(b0.x, kvB, s0.x));
        s0.y = fmaf(a0.y, kvA, fmaf(b0.y, kvB, s0.y));
        s0.z = fmaf(a0.z, kvA, fmaf(b0.z, kvB, s0.z));
        s0.w = fmaf(a0.w, kvA, fmaf(b0.w, kvB, s0.w));
        s1.x = fmaf(a1.x, kvA, fmaf(b1.x, kvB, s1.x));
        s1.y = fmaf(a1.y, kvA, fmaf(b1.y, kvB, s1.y));
        s1.z = fmaf(a1.z, kvA, fmaf(b1.z, kvB, s1.z));
        s1.w = fmaf(a1.w, kvA, fmaf(b1.w, kvB, s1.w));
        s2.x = fmaf(a2.x, kvA, fmaf(b2.x, kvB, s2.x));
        s2.y = fmaf(a2.y, kvA, fmaf(b2.y, kvB, s2.y));
        s2.z = fmaf(a2.z, kvA, fmaf(b2.z, kvB, s2.z));
        s2.w = fmaf(a2.w, kvA, fmaf(b2.w, kvB, s2.w));
        s3.x = fmaf(a3.x, kvA, fmaf(b3.x, kvB, s3.x));
        s3.y = fmaf(a3.y, kvA, fmaf(b3.y, kvB, s3.y));
        s3.z = fmaf(a3.z, kvA, fmaf(b3.z, kvB, s3.z));
        s3.w = fmaf(a3.w, kvA, fmaf(b3.w, kvB, s3.w));
    }

    // block pre-reduction in shared, then 512 global atomics per block
    const int b0i = 4 * lane;
    atomicAdd(&sblk[b0i + 0],       s0.x); atomicAdd(&sblk[b0i + 1],       s0.y);
    atomicAdd(&sblk[b0i + 2],       s0.z); atomicAdd(&sblk[b0i + 3],       s0.w);
    atomicAdd(&sblk[128 + b0i + 0], s1.x); atomicAdd(&sblk[128 + b0i + 1], s1.y);
    atomicAdd(&sblk[128 + b0i + 2], s1.z); atomicAdd(&sblk[128 + b0i + 3], s1.w);
    atomicAdd(&sblk[256 + b0i + 0], s2.x); atomicAdd(&sblk[256 + b0i + 1], s2.y);
    atomicAdd(&sblk[256 + b0i + 2], s2.z); atomicAdd(&sblk[256 + b0i + 3], s2.w);
    atomicAdd(&sblk[384 + b0i + 0], s3.x); atomicAdd(&sblk[384 + b0i + 1], s3.y);
    atomicAdd(&sblk[384 + b0i + 2], s3.z); atomicAdd(&sblk[384 + b0i + 3], s3.w);
    __syncthreads();
    for (int i = tid; i < D; i += TPB) atomicAdd(&g_s[i], sblk[i]);
}

// ---------------------------------------------------------------------------
// K2: t[d] = sum_j value_w[j][d] * s[j]  (32 blocks, 16 j's each, atomic merge)
//     c    = value_b · s                 (block 0)
// ---------------------------------------------------------------------------
__global__ void k2(const float* __restrict__ vw, const float* __restrict__ vb) {
    const int tid = threadIdx.x;            // 512 threads
    const int j0 = blockIdx.x * 16;
    float acc = 0.0f;
#pragma unroll
    for (int j = 0; j < 16; j++)
        acc = fmaf(vw[(size_t)(j0 + j) * D + tid], g_s[j0 + j], acc);
    atomicAdd(&g_t[tid], acc);

    if (blockIdx.x == 0) {
        __shared__ float red[D];
        red[tid] = vb[tid] * g_s[tid];
        __syncthreads();
        for (int sft = 256; sft > 0; sft >>= 1) {
            if (tid < sft) red[tid] += red[tid + sft];
            __syncthreads();
        }
        if (tid == 0) g_c = red[0];
    }
}

// ---------------------------------------------------------------------------
// K3: pass 2, DESCENDING row order (L2 ping-pong against k1's ascending
// stream and against the next graph replay's k1).
// x[n] = inputs[n]·t + c, track global max.
// ---------------------------------------------------------------------------
__global__ void __launch_bounds__(TPB, 4)
k3(const float* __restrict__ inp) {
    const int tid = threadIdx.x;
    const int lane = tid & 31;
    const int gw = (blockIdx.x * TPB + tid) >> 5;

    const float4* __restrict__ tp = (const float4*)g_t;
    const float4 w0 = tp[lane],      w1 = tp[lane + 32],
                 w2 = tp[lane + 64], w3 = tp[lane + 96];
    const float c = g_c;
    float maxv = -3.4e38f;

    for (int p = NPAIRS - 1 - gw; p >= 0; p -= K3_WARPS) {
        const float4* __restrict__ rA = (const float4*)inp + (size_t)(2 * p) * (D / 4);
        const float4* __restrict__ rB = rA + (D / 4);
        const float4 a0 = rA[lane],      a1 = rA[lane + 32],
                     a2 = rA[lane + 64], a3 = rA[lane + 96];
        const float4 b0 = rB[lane],      b1 = rB[lane + 32],
                     b2 = rB[lane + 64], b3 = rB[lane + 96];

        float dA = (dot4(a0, w0) + dot4(a1, w1)) + (dot4(a2, w2) + dot4(a3, w3));
        float dB = (dot4(b0, w0) + dot4(b1, w1)) + (dot4(b2, w2) + dot4(b3, w3));
#pragma unroll
        for (int o = 16; o; o >>= 1) {
            dA += __shfl_xor_sync(FULL, dA, o);
            dB += __shfl_xor_sync(FULL, dB, o);
        }
        const float xA = dA + c;
        const float xB = dB + c;
        if (lane == 0) {
            g_x[2 * p]     = xA;
            g_x[2 * p + 1] = xB;
        }
        maxv = fmaxf(maxv, fmaxf(xA, xB));
    }

    if (lane == 0) {
        unsigned u = __float_as_uint(maxv);
        unsigned key = (u & 0x80000000u) ? ~u : (u | 0x80000000u);
        atomicMax(&g_maxkey, key);
    }
}

// ---------------------------------------------------------------------------
// K45: fused exp/sum/divide. 64 fully-resident blocks; internal spin barrier.
// ---------------------------------------------------------------------------
__global__ void k45(float* __restrict__ out) {
    const unsigned key = g_maxkey;
    const unsigned ub = (key & 0x80000000u) ? (key & 0x7fffffffu) : ~key;
    const float gmax = __uint_as_float(ub);

    const int i = blockIdx.x * blockDim.x + threadIdx.x;   // 16384 threads
    const float4 v = ((const float4*)g_x)[i];
    float4 e;
    e.x = expf(v.x - gmax); e.y = expf(v.y - gmax);
    e.z = expf(v.z - gmax); e.w = expf(v.w - gmax);

    float ws = warp_sum((e.x + e.y) + (e.z + e.w));
    __shared__ float sh[8];
    const int lane = threadIdx.x & 31, w = threadIdx.x >> 5;
    if (lane == 0) sh[w] = ws;
    __syncthreads();
    if (w == 0) {
        float s = (lane < 8) ? sh[lane] : 0.0f;
        s = warp_sum(s);
        if (lane == 0) {
            atomicAdd(&g_sumexp, s);
            __threadfence();
            atomicAdd(&g_done, 1u);
        }
    }

    // grid-wide spin: all 64 CTAs resident, cannot deadlock
    if (threadIdx.x == 0) {
        while (*((volatile unsigned*)&g_done) < (unsigned)gridDim.x) { }
    }
    __syncthreads();
    __threadfence();

    const float inv = 1.0f / (*((volatile float*)&g_sumexp));
    float4 r;
    r.x = e.x * inv; r.y = e.y * inv; r.z = e.z * inv; r.w = e.w * inv;
    ((float4*)out)[i] = r;
}

// ---------------------------------------------------------------------------
extern "C" void kernel_launch(void* const* d_in, const int* in_sizes, int n_in,
                              void* d_out, int out_size) {
    (void)in_sizes; (void)n_in; (void)out_size;
    const float* inp = (const float*)d_in[0];   // [N, D]
    const float* kw  = (const float*)d_in[1];   // [1, D]
    const float* kb  = (const float*)d_in[2];   // [1]
    const float* vw  = (const float*)d_in[3];   // [D, D]
    const float* vb  = (const float*)d_in[4];   // [D]
    float* out = (float*)d_out;                 // [N, 1]

    k_init<<<1, D>>>();
    k1<<<K1_BLOCKS, TPB>>>(inp, kw, kb);
    k2<<<32, D>>>(vw, vb);
    k3<<<K3_BLOCKS, TPB>>>(inp);
    k45<<<K45_BLOCKS, TPB>>>(out);
}

// round 9
// speedup vs baseline: 1.4048x; 1.0007x over previous
#include <cuda_runtime.h>
#include <cstdint>

#define FULL 0xffffffffu

constexpr int N = 65536;
constexpr int D = 512;
constexpr int NPAIRS = N / 2;                    // 32768 row pairs
constexpr int TPB  = 256;                        // 8 warps
constexpr int GRID = 444;                        // 3 CTAs/SM * 148 SMs — co-residency
                                                 // guaranteed under weak conditions
constexpr int GW   = GRID * (TPB / 32);          // 3552 warps total

// ---------------------------------------------------------------------------
// Persistent device state (allocation-free). All invariants restored by the
// end of each launch so graph replays see identical initial state:
//   g_s, g_t, g_maxkey : zeroed in post-barrier windows below
//   g_cnt              : self-resetting (last arriver)
//   g_flag             : monotonic, observed at kernel entry
//   g_c, g_part        : overwrite-only (no reset needed)
// ---------------------------------------------------------------------------
__device__ __align__(16) float g_s[D];
__device__ __align__(16) float g_t[D];
__device__ float    g_c;
__device__ unsigned g_maxkey;
__device__ __align__(16) float g_part[64];
__device__ __align__(16) float g_x[N];
__device__ unsigned g_cnt[4];
__device__ volatile unsigned g_flag[4];

__device__ __forceinline__ float warp_sum(float v) {
#pragma unroll
    for (int o = 16; o; o >>= 1) v += __shfl_xor_sync(FULL, v, o);
    return v;
}
__device__ __forceinline__ float dot4(float4 a, float4 w) {
    return fmaf(a.w, w.w, fmaf(a.z, w.z, fmaf(a.y, w.y, a.x * w.x)));
}

// Grid-wide barrier, graph-replay-safe. f = flag value observed at kernel
// entry (flag i cannot be bumped until every CTA reaches barrier i, and every
// CTA reads its f before its own arrival). Last arriver resets the counter,
// then releases everyone by bumping the flag.
__device__ __forceinline__ void gbar(int i, unsigned f) {
    __syncthreads();
    if (threadIdx.x == 0) {
        __threadfence();
        unsigned pos = atomicAdd(&g_cnt[i], 1u);
        if (pos == GRID - 1) {
            g_cnt[i] = 0;
            __threadfence();
            g_flag[i] = f + 1;
        } else {
            while (g_flag[i] == f) { __nanosleep(64); }
        }
        __threadfence();
    }
    __syncthreads();
}

// ---------------------------------------------------------------------------
// Fused persistent kernel: all phases in one launch.
// ---------------------------------------------------------------------------
__global__ void __launch_bounds__(TPB, 3)
fused(const float* __restrict__ inp, const float* __restrict__ kw,
      const float* __restrict__ kb,  const float* __restrict__ vw,
      const float* __restrict__ vb,  float* __restrict__ out) {
    __shared__ __align__(16) float s_wt[D];      // key_w in phase A, t in phase C
    __shared__ float s_red[D];
    __shared__ float s_p[8];

    const int tid  = threadIdx.x;
    const int lane = tid & 31;
    const int bid  = blockIdx.x;
    const int gw   = (bid * TPB + tid) >> 5;

    // observe release flags before any barrier traffic (replay-safe)
    unsigned f0 = 0, f1 = 0, f2 = 0, f3 = 0;
    if (tid == 0) { f0 = g_flag[0]; f1 = g_flag[1]; f2 = g_flag[2]; f3 = g_flag[3]; }

    // stage key_w into smem; zero reduction buffer
    s_wt[tid] = kw[tid]; s_wt[tid + 256] = kw[tid + 256];
    s_red[tid] = 0.0f;   s_red[tid + 256] = 0.0f;
    __syncthreads();

    const float kb0 = kb[0];
    const float4* __restrict__ sw4 = (const float4*)s_wt;
    const float4* __restrict__ inp4 = (const float4*)inp;

    // ---------------- Phase A: s = sum_n inputs[n] * k[n], ASCENDING -------
    {
        float4 s0 = {0,0,0,0}, s1 = {0,0,0,0}, s2 = {0,0,0,0}, s3 = {0,0,0,0};
        for (int p = gw; p < NPAIRS; p += GW) {
            const float4* __restrict__ rA = inp4 + (size_t)(2 * p) * (D / 4);
            const float4* __restrict__ rB = rA + (D / 4);
            const float4 a0 = rA[lane],      a1 = rA[lane + 32],
                         a2 = rA[lane + 64], a3 = rA[lane + 96];
            const float4 b0 = rB[lane],      b1 = rB[lane + 32],
                         b2 = rB[lane + 64], b3 = rB[lane + 96];

            float4 w = sw4[lane];
            float dA = dot4(a0, w),  dB = dot4(b0, w);
            w = sw4[lane + 32]; dA += dot4(a1, w); dB += dot4(b1, w);
            w = sw4[lane + 64]; dA += dot4(a2, w); dB += dot4(b2, w);
            w = sw4[lane + 96]; dA += dot4(a3, w); dB += dot4(b3, w);
#pragma unroll
            for (int o = 16; o; o >>= 1) {
                dA += __shfl_xor_sync(FULL, dA, o);
                dB += __shfl_xor_sync(FULL, dB, o);
            }
            const float kvA = dA + kb0, kvB = dB + kb0;

            s0.x = fmaf(a0.x, kvA, fmaf(b0.x, kvB, s0.x));
            s0.y = fmaf(a0.y, kvA, fmaf(b0.y, kvB, s0.y));
            s0.z = fmaf(a0.z, kvA, fmaf(b0.z, kvB, s0.z));
            s0.w = fmaf(a0.w, kvA, fmaf(b0.w, kvB, s0.w));
            s1.x = fmaf(a1.x, kvA, fmaf(b1.x, kvB, s1.x));
            s1.y = fmaf(a1.y, kvA, fmaf(b1.y, kvB, s1.y));
            s1.z = fmaf(a1.z, kvA, fmaf(b1.z, kvB, s1.z));
            s1.w = fmaf(a1.w, kvA, fmaf(b1.w, kvB, s1.w));
            s2.x = fmaf(a2.x, kvA, fmaf(b2.x, kvB, s2.x));
            s2.y = fmaf(a2.y, kvA, fmaf(b2.y, kvB, s2.y));
            s2.z = fmaf(a2.z, kvA, fmaf(b2.z, kvB, s2.z));
            s2.w = fmaf(a2.w, kvA, fmaf(b2.w, kvB, s2.w));
            s3.x = fmaf(a3.x, kvA, fmaf(b3.x, kvB, s3.x));
            s3.y = fmaf(a3.y, kvA, fmaf(b3.y, kvB, s3.y));
            s3.z = fmaf(a3.z, kvA, fmaf(b3.z, kvB, s3.z));
            s3.w = fmaf(a3.w, kvA, fmaf(b3.w, kvB, s3.w));
        }
        const int b0i = 4 * lane;
        atomicAdd(&s_red[b0i + 0],       s0.x); atomicAdd(&s_red[b0i + 1],       s0.y);
        atomicAdd(&s_red[b0i + 2],       s0.z); atomicAdd(&s_red[b0i + 3],       s0.w);
        atomicAdd(&s_red[128 + b0i + 0], s1.x); atomicAdd(&s_red[128 + b0i + 1], s1.y);
        atomicAdd(&s_red[128 + b0i + 2], s1.z); atomicAdd(&s_red[128 + b0i + 3], s1.w);
        atomicAdd(&s_red[256 + b0i + 0], s2.x); atomicAdd(&s_red[256 + b0i + 1], s2.y);
        atomicAdd(&s_red[256 + b0i + 2], s2.z); atomicAdd(&s_red[256 + b0i + 3], s2.w);
        atomicAdd(&s_red[384 + b0i + 0], s3.x); atomicAdd(&s_red[384 + b0i + 1], s3.y);
        atomicAdd(&s_red[384 + b0i + 2], s3.z); atomicAdd(&s_red[384 + b0i + 3], s3.w);
        __syncthreads();
        atomicAdd(&g_s[tid], s_red[tid]);
        atomicAdd(&g_s[tid + 256], s_red[tid + 256]);
    }

    gbar(0, f0);   // s complete

    // ---------------- Phase B: t = vw^T s (64 CTAs), c = vb.s (CTA 64) -----
    if (bid < 64) {
        const int jb = bid >> 1;                  // 32 j-blocks of 16
        const int d  = (bid & 1) * 256 + tid;     // 256 d's per CTA
        const int j0 = jb * 16;
        float acc = 0.0f;
#pragma unroll
        for (int j = 0; j < 16; j++)
            acc = fmaf(vw[(size_t)(j0 + j) * D + d], g_s[j0 + j], acc);
        atomicAdd(&g_t[d], acc);
    } else if (bid == 64) {
        float v = vb[tid] * g_s[tid] + vb[tid + 256] * g_s[tid + 256];
        v = warp_sum(v);
        if (lane == 0) s_p[tid >> 5] = v;
        __syncthreads();
        if (tid < 32) {
            float s = (lane < 8) ? s_p[lane] : 0.0f;
            s = warp_sum(s);
            if (lane == 0) g_c = s;
        }
    }

    gbar(1, f1);   // t and c complete

    if (bid == 0) { g_s[tid] = 0.0f; g_s[tid + 256] = 0.0f; }   // reset for next replay

    // stage t into smem (overwrites key_w — phase A done)
    s_wt[tid] = g_t[tid]; s_wt[tid + 256] = g_t[tid + 256];
    __syncthreads();
    const float c = g_c;

    // ---------------- Phase C: x = inputs . t + c, DESCENDING (L2 ping-pong)
    {
        float maxv = -3.4e38f;
        for (int p = NPAIRS - 1 - gw; p >= 0; p -= GW) {
            const float4* __restrict__ rA = inp4 + (size_t)(2 * p) * (D / 4);
            const float4* __restrict__ rB = rA + (D / 4);
            const float4 a0 = rA[lane],      a1 = rA[lane + 32],
                         a2 = rA[lane + 64], a3 = rA[lane + 96];
            const float4 b0 = rB[lane],      b1 = rB[lane + 32],
                         b2 = rB[lane + 64], b3 = rB[lane + 96];

            float4 w = sw4[lane];
            float dA = dot4(a0, w),  dB = dot4(b0, w);
            w = sw4[lane + 32]; dA += dot4(a1, w); dB += dot4(b1, w);
            w = sw4[lane + 64]; dA += dot4(a2, w); dB += dot4(b2, w);
            w = sw4[lane + 96]; dA += dot4(a3, w); dB += dot4(b3, w);
#pragma unroll
            for (int o = 16; o; o >>= 1) {
                dA += __shfl_xor_sync(FULL, dA, o);
                dB += __shfl_xor_sync(FULL, dB, o);
            }
            const float xA = dA + c, xB = dB + c;
            if (lane == 0) {
                g_x[2 * p]     = xA;
                g_x[2 * p + 1] = xB;
            }
            maxv = fmaxf(maxv, fmaxf(xA, xB));
        }
        if (lane == 0) {
            unsigned u = __float_as_uint(maxv);
            unsigned key = (u & 0x80000000u) ? ~u : (u | 0x80000000u);
            atomicMax(&g_maxkey, key);
        }
    }

    gbar(2, f2);   // x and max complete

    if (bid == 1) { g_t[tid] = 0.0f; g_t[tid + 256] = 0.0f; }   // reset for next replay

    // ---------------- Phase D1: e = exp(x - max) (64 CTAs), block partials -
    if (bid < 64) {
        const unsigned key = g_maxkey;
        const unsigned ub = (key & 0x80000000u) ? (key & 0x7fffffffu) : ~key;
        const float gmax = __uint_as_float(ub);

        const int g = bid * TPB + tid;           // < 16384 float4 elems
        const float4 v = ((const float4*)g_x)[g];
        float4 e;
        e.x = expf(v.x - gmax); e.y = expf(v.y - gmax);
        e.z = expf(v.z - gmax); e.w = expf(v.w - gmax);
        ((float4*)g_x)[g] = e;

        float ws = warp_sum((e.x + e.y) + (e.z + e.w));
        if (lane == 0) s_p[tid >> 5] = ws;
        __syncthreads();
        if (tid < 32) {
            float s = (lane < 8) ? s_p[lane] : 0.0f;
            s = warp_sum(s);
            if (lane == 0) g_part[bid] = s;
        }
    }

    gbar(3, f3);   // e and partials complete

    if (bid == 2 && tid == 0) g_maxkey = 0u;     // reset for next replay

    // ---------------- Phase D2: out = e / sumexp ---------------------------
    if (bid < 64) {
        const float4* __restrict__ pp = (const float4*)g_part;
        float sum = 0.0f;
#pragma unroll
        for (int i = 0; i < 16; i++) {
            const float4 q = pp[i];
            sum += (q.x + q.y) + (q.z + q.w);
        }
        const float inv = 1.0f / sum;
        const int g = bid * TPB + tid;
        const float4 e = ((const float4*)g_x)[g];
        float4 r;
        r.x = e.x * inv; r.y = e.y * inv; r.z = e.z * inv; r.w = e.w * inv;
        ((float4*)out)[g] = r;
    }
}

// ---------------------------------------------------------------------------
extern "C" void kernel_launch(void* const* d_in, const int* in_sizes, int n_in,
                              void* d_out, int out_size) {
    (void)in_sizes; (void)n_in; (void)out_size;
    const float* inp = (const float*)d_in[0];   // [N, D]
    const float* kw  = (const float*)d_in[1];   // [1, D]
    const float* kb  = (const float*)d_in[2];   // [1]
    const float* vw  = (const float*)d_in[3];   // [D, D]
    const float* vb  = (const float*)d_in[4];   // [D]
    float* out = (float*)d_out;                 // [N, 1]

    fused<<<GRID, TPB>>>(inp, kw, kb, vw, vb, out);
}